// round 13
// baseline (speedup 1.0000x reference)
#include <cuda_runtime.h>

#define TS 32
#define HALO 5
#define IT 42                 // tile buffer is 42x42
#define NT 256
#define HI 1024
#define WI 1024
#define HW (HI*WI)
#define NPIX (8*3*HW)         // 25165824
#define NTHUMB (8*3*256*256)  // 1572864

typedef unsigned long long u64;

__device__ __forceinline__ u64 pack2(float lo, float hi){
    u64 d;
    asm("mov.b64 %0, {%1, %2};" : "=l"(d)
        : "r"(__float_as_uint(lo)), "r"(__float_as_uint(hi)));
    return d;
}
__device__ __forceinline__ void unpack2(u64 v, float &lo, float &hi){
    unsigned a, b;
    asm("mov.b64 {%0, %1}, %2;" : "=r"(a), "=r"(b) : "l"(v));
    lo = __uint_as_float(a); hi = __uint_as_float(b);
}
// {hi(a), lo(b)}
__device__ __forceinline__ u64 pack_hl(u64 a, u64 b){
    unsigned a0,a1,b0,b1;
    asm("mov.b64 {%0,%1}, %2;" : "=r"(a0),"=r"(a1) : "l"(a));
    asm("mov.b64 {%0,%1}, %2;" : "=r"(b0),"=r"(b1) : "l"(b));
    u64 d; asm("mov.b64 %0, {%1,%2};" : "=l"(d) : "r"(a1),"r"(b0));
    return d;
}
__device__ __forceinline__ u64 fma2(u64 a, u64 b, u64 c){
    u64 d;
    asm("fma.rn.f32x2 %0, %1, %2, %3;" : "=l"(d) : "l"(a), "l"(b), "l"(c));
    return d;
}
__device__ __forceinline__ u64 add2(u64 a, u64 b){
    u64 d;
    asm("add.rn.f32x2 %0, %1, %2;" : "=l"(d) : "l"(a), "l"(b));
    return d;
}
__device__ __forceinline__ float lk(float v){ return fmaxf(v, 0.2f*v); } // exact leaky

struct SM {
    float a[3][IT][IT];       // [ch][row][col] 21168 B
    float b[3][IT][IT];       //                21168 B
    u64   wsp[5][3][3][9];    // splatted conv3 weights {w,w} [S][o][i][kh*3+kw]
    u64   bsp[5][3];          // splatted biases
    float ftail[72];          // feat[420..491]
};                            // 45984 B static

// One residual 3x3 block: dst = leaky(src + conv3x3(src)), zero-masked to image.
// STAGE-INVARIANT fixed region: every stage computes rows/cols 1..40 with the
// SAME per-thread mapping (c = 1+2q odd, y = 1+4g, 200 items). Poisoned border
// values advance inward exactly 1 px/stage; after 5 stages the valid region is
// [5,36]^2 = exactly the output tile. Identical per-stage offsets let ptxas
// compute LDS/STS addresses once and reuse across all five stages.
// 2-col x 4-row micro-tile: kw=+/-1 tap pairs are aligned LDS.64; center pair
// is one register merge; residual folded from center pairs (no extra loads).
template<int S, bool EDGE>
__device__ __forceinline__ void stage(const float (&src)[3][IT][IT],
                                      float (&dst)[3][IT][IT],
                                      const u64 (&wsp)[5][3][3][9],
                                      const u64 (&bsp)[5][3],
                                      int gy0, int gx0, int tid)
{
    if (tid < 200){
        const int c = 1 + 2*(tid % 20);     // cols c, c+1 (c odd)
        const int y = 1 + 4*(tid / 20);     // rows y..y+3 (y in 1..37)

        u64 A[3][4];                        // A[o][r] = out pair {c, c+1} at row y+r
        #pragma unroll
        for (int o = 0; o < 3; o++){
            const u64 bb = bsp[S][o];
            #pragma unroll
            for (int r = 0; r < 4; r++) A[o][r] = bb;
        }

        #pragma unroll
        for (int i = 0; i < 3; i++){
            u64 Q0[6], Q1[6], C[6];         // rows y-1 .. y+4 (0..41: in-bounds)
            #pragma unroll
            for (int r = 0; r < 6; r++){
                Q0[r] = *(const u64*)&src[i][y-1+r][c-1];   // aligned {c-1,c}
                Q1[r] = *(const u64*)&src[i][y-1+r][c+1];   // aligned {c+1,c+2}
            }
            #pragma unroll
            for (int r = 0; r < 6; r++) C[r] = pack_hl(Q0[r], Q1[r]);  // {c,c+1}
            #pragma unroll
            for (int o = 0; o < 3; o++)
                #pragma unroll
                for (int kh = 0; kh < 3; kh++){
                    const u64 wl = wsp[S][o][i][kh*3+0];    // broadcast LDS.64
                    const u64 wc = wsp[S][o][i][kh*3+1];
                    const u64 wr = wsp[S][o][i][kh*3+2];
                    #pragma unroll
                    for (int r = 0; r < 4; r++){
                        A[o][r] = fma2(wl, Q0[r+kh], A[o][r]);
                        A[o][r] = fma2(wc, C [r+kh], A[o][r]);
                        A[o][r] = fma2(wr, Q1[r+kh], A[o][r]);
                    }
                }
            // residual for matching channel: src pair {c,c+1} at row y+r = C[r+1]
            #pragma unroll
            for (int r = 0; r < 4; r++) A[i][r] = add2(A[i][r], C[r+1]);
        }

        const int gxl = gx0 + c;
        #pragma unroll
        for (int o = 0; o < 3; o++)
            #pragma unroll
            for (int r = 0; r < 4; r++){
                const int Y = y + r;
                float lo, hi; unpack2(A[o][r], lo, hi);
                lo = lk(lo);
                hi = lk(hi);
                if (EDGE){
                    const int gy = gy0 + Y;
                    const bool iny = (unsigned)gy < (unsigned)HI;
                    if (!(iny && (unsigned)gxl     < (unsigned)WI)) lo = 0.f;
                    if (!(iny && (unsigned)(gxl+1) < (unsigned)WI)) hi = 0.f;
                }
                dst[o][Y][c]   = lo;
                dst[o][Y][c+1] = hi;
            }
    }
}

__device__ __forceinline__ float att_eval(const float* c, float h, float w, float xi)
{
    float Ah = fmaf(h, fmaf(c[0],h, fmaf(c[1],w, fmaf(c[2],xi,c[3]))),
               fmaf(w, fmaf(c[4],w, fmaf(c[5],xi,c[6])),
               fmaf(xi, fmaf(c[7],xi,c[8]), c[9])));
    float Bw = fmaf(w, fmaf(c[10],w, fmaf(c[11],xi,c[12])),
               fmaf(xi, fmaf(c[13],xi,c[14]), c[15]));
    float Cx = fmaf(xi, fmaf(c[16],xi,c[17]), c[18]);
    return fmaf(h, Ah, fmaf(w, Bw, fmaf(xi, Cx, c[19])));
}

template<bool EDGE>
__device__ __forceinline__ void run_stages(SM& sm, int gy0, int gx0, int tid)
{
    stage<0,EDGE>(sm.a, sm.b, sm.wsp, sm.bsp, gy0, gx0, tid); __syncthreads();
    stage<1,EDGE>(sm.b, sm.a, sm.wsp, sm.bsp, gy0, gx0, tid); __syncthreads();
    stage<2,EDGE>(sm.a, sm.b, sm.wsp, sm.bsp, gy0, gx0, tid); __syncthreads();
    stage<3,EDGE>(sm.b, sm.a, sm.wsp, sm.bsp, gy0, gx0, tid); __syncthreads();
    stage<4,EDGE>(sm.a, sm.b, sm.wsp, sm.bsp, gy0, gx0, tid); __syncthreads();
}

__global__ __launch_bounds__(NT, 3)
void fused_kernel(const float* __restrict__ x,
                  const float* __restrict__ feature,
                  float* __restrict__ out)
{
    __shared__ SM sm;

    const int tile   = blockIdx.x;       // 0..1023
    const int bidx   = blockIdx.y;       // 0..7
    const int tilesX = WI / TS;          // 32
    const int ty = tile / tilesX, tx = tile % tilesX;
    const int gy0 = ty*TS - HALO, gx0 = tx*TS - HALO;
    const int tid = threadIdx.x;
    const bool edge = (ty == 0) | (ty == tilesX-1) | (tx == 0) | (tx == tilesX-1);

    // feature -> splatted conv weights / biases + tail
    const float* fb = feature + bidx*492;
    for (int idx = tid; idx < 5*84; idx += NT){
        int s = idx / 84, j = idx % 84;
        float f = fb[s*84 + j];
        if (j < 81){
            int o = j / 27, i = (j % 27) / 9, t = j % 9;
            sm.wsp[s][o][i][t] = pack2(f, f);
        } else {
            sm.bsp[s][j-81] = pack2(f, f);
        }
    }
    for (int idx = tid; idx < 72; idx += NT) sm.ftail[idx] = fb[420 + idx];

    // input tile (zero-padded at image boundary) -> smem A rows 0..41
    const float* xb = x + (size_t)bidx*3*HW;
    for (int p = tid; p < 3*IT*IT; p += NT){
        int cch = p / (IT*IT);
        int r   = p % (IT*IT);
        int yy = r / IT, xx = r % IT;            // lanes -> xx: coalesced LDG
        int gy = gy0 + yy, gx = gx0 + xx;
        float v = 0.f;
        if (((unsigned)gy < (unsigned)HI) && ((unsigned)gx < (unsigned)WI))
            v = xb[(size_t)cch*HW + (size_t)gy*WI + gx];
        sm.a[cch][yy][xx] = v;
    }
    __syncthreads();

    if (edge) run_stages<true >(sm, gy0, gx0, tid);
    else      run_stages<false>(sm, gy0, gx0, tid);
    // result in sm.b, valid rows/cols [HALO, HALO+TS)

    float k1[9], b1[3];
    #pragma unroll
    for (int j = 0; j < 9; j++) k1[j] = sm.ftail[j];
    #pragma unroll
    for (int o = 0; o < 3; o++) b1[o] = sm.ftail[9 + o];
    float ca[20], cb[20], cc[20];
    #pragma unroll
    for (int j = 0; j < 20; j++){
        ca[j] = sm.ftail[12 + j];
        cb[j] = sm.ftail[32 + j];
        cc[j] = sm.ftail[52 + j];
    }

    const float invH = 1.0f / HI, invW = 1.0f / WI;
    for (int p = tid; p < TS*TS; p += NT){
        int y  = HALO + p / TS;
        int xq = HALO + p % TS;
        int gy = gy0 + y, gx = gx0 + xq;

        float v0 = sm.b[0][y][xq];
        float v1 = sm.b[1][y][xq];
        float v2 = sm.b[2][y][xq];

        float t0 = lk(v0 + k1[0]*v0 + k1[1]*v1 + k1[2]*v2 + b1[0]);
        float t1 = lk(v1 + k1[3]*v0 + k1[4]*v1 + k1[5]*v2 + b1[1]);
        float t2 = lk(v2 + k1[6]*v0 + k1[7]*v1 + k1[8]*v2 + b1[2]);

        size_t pix = (size_t)gy*WI + gx;
        float xf0 = xb[pix]        + t0;   // global residual (original x)
        float xf1 = xb[HW + pix]   + t1;
        float xf2 = xb[2*HW + pix] + t2;

        float h  = (float)gy * invH;
        float w_ = (float)gx * invW;

        size_t base = (size_t)bidx*3*HW + pix;
        out[base]        = fmaf(xf0, att_eval(ca, h, w_, xf0), xf0);
        out[base + HW]   = fmaf(xf1, att_eval(cb, h, w_, xf1), xf1);
        out[base + 2*HW] = fmaf(xf2, att_eval(cc, h, w_, xf2), xf2);
    }
}

__global__ void copy_thumb_kernel(const float4* __restrict__ src, float4* __restrict__ dst)
{
    int i = blockIdx.x * blockDim.x + threadIdx.x;
    if (i < NTHUMB/4) dst[i] = src[i];
}

extern "C" void kernel_launch(void* const* d_in, const int* in_sizes, int n_in,
                              void* d_out, int out_size)
{
    const float* x     = (const float*)d_in[0];
    const float* thumb = (const float*)d_in[1];
    const float* feat  = (const float*)d_in[2];
    float* out = (float*)d_out;

    // thumb copy FIRST so ncu's skip-5 sample lands on fused_kernel
    int nv4 = NTHUMB/4;
    copy_thumb_kernel<<<(nv4 + 255)/256, 256>>>((const float4*)thumb,
                                                (float4*)(out + NPIX));

    dim3 grid((HI/TS)*(WI/TS), 8);
    fused_kernel<<<grid, NT>>>(x, feat, out);
}

// round 14
// speedup vs baseline: 1.1208x; 1.1208x over previous
#include <cuda_runtime.h>

#define TS 64
#define HALO 5
#define IT 74                 // tile buffer 74x74
#define NT 672
#define HI 1024
#define WI 1024
#define HW (HI*WI)
#define NPIX (8*3*HW)         // 25165824
#define NTHUMB (8*3*256*256)  // 1572864

typedef unsigned long long u64;

__device__ __forceinline__ u64 pack2(float lo, float hi){
    u64 d;
    asm("mov.b64 %0, {%1, %2};" : "=l"(d)
        : "r"(__float_as_uint(lo)), "r"(__float_as_uint(hi)));
    return d;
}
__device__ __forceinline__ void unpack2(u64 v, float &lo, float &hi){
    unsigned a, b;
    asm("mov.b64 {%0, %1}, %2;" : "=r"(a), "=r"(b) : "l"(v));
    lo = __uint_as_float(a); hi = __uint_as_float(b);
}
// {hi(a), lo(b)}
__device__ __forceinline__ u64 pack_hl(u64 a, u64 b){
    unsigned a0,a1,b0,b1;
    asm("mov.b64 {%0,%1}, %2;" : "=r"(a0),"=r"(a1) : "l"(a));
    asm("mov.b64 {%0,%1}, %2;" : "=r"(b0),"=r"(b1) : "l"(b));
    u64 d; asm("mov.b64 %0, {%1,%2};" : "=l"(d) : "r"(a1),"r"(b0));
    return d;
}
__device__ __forceinline__ u64 fma2(u64 a, u64 b, u64 c){
    u64 d;
    asm("fma.rn.f32x2 %0, %1, %2, %3;" : "=l"(d) : "l"(a), "l"(b), "l"(c));
    return d;
}
__device__ __forceinline__ u64 add2(u64 a, u64 b){
    u64 d;
    asm("add.rn.f32x2 %0, %1, %2;" : "=l"(d) : "l"(a), "l"(b));
    return d;
}
__device__ __forceinline__ float lk(float v){ return fmaxf(v, 0.2f*v); } // exact leaky

struct SMD {
    u64   wsp[5][3][3][9];    // splatted conv3 weights {w,w} [S][o][i][kh*3+kw]
    u64   bsp[5][3];          // splatted biases
    float ftail[72];          // feat[420..491]
    float a[3][IT][IT];       // [ch][row][col] 65712 B
    float b[3][IT][IT];       //                65712 B
};                            // ~135.1 KB dynamic shared

// One residual 3x3 block: dst = leaky(src + conv3x3(src)), zero-masked to image.
// 2col x 4row micro-tile (8 px), col base odd: kw=-1 ({c-1,c}) / kw=+1
// ({c+1,c+2}) tap pairs are aligned LDS.64; center is one register merge;
// residual folded from center pairs. Shrinking regions: cols via QMIN=S>>1
// (36-2*QMIN pairs), rows [S+1 .. 72-S] in clamped 4-row groups. Junk/stale
// border cells advance inward >=1 px/stage; final valid region = [5,68]^2.
template<int S, bool EDGE>
__device__ __forceinline__ void stage(const float (&src)[3][IT][IT],
                                      float (&dst)[3][IT][IT],
                                      const u64 (&wsp)[5][3][3][9],
                                      const u64 (&bsp)[5][3],
                                      int gy0, int gx0, int tid)
{
    constexpr int QMIN = S >> 1;
    constexpr int NP   = 36 - 2*QMIN;        // col pairs: 36,36,34,34,32
    constexpr int NR   = 72 - 2*S;           // rows needed
    constexpr int RG   = (NR + 3) / 4;       // row groups: 18,18,17,17,16
    if (tid < NP*RG){
        const int c = 1 + 2*(QMIN + tid % NP);   // odd col base
        int y = (S + 1) + 4*(tid / NP);
        if (y > 69 - S) y = 69 - S;              // clamp: rows stay in [S+1,72-S]

        u64 A[3][4];
        #pragma unroll
        for (int o = 0; o < 3; o++){
            const u64 bb = bsp[S][o];
            #pragma unroll
            for (int r = 0; r < 4; r++) A[o][r] = bb;
        }

        #pragma unroll
        for (int i = 0; i < 3; i++){
            u64 Q0[6], Q1[6], C[6];              // rows y-1 .. y+4
            #pragma unroll
            for (int r = 0; r < 6; r++){
                Q0[r] = *(const u64*)&src[i][y-1+r][c-1];   // aligned {c-1,c}
                Q1[r] = *(const u64*)&src[i][y-1+r][c+1];   // aligned {c+1,c+2}
            }
            #pragma unroll
            for (int r = 0; r < 6; r++) C[r] = pack_hl(Q0[r], Q1[r]);  // {c,c+1}
            #pragma unroll
            for (int o = 0; o < 3; o++)
                #pragma unroll
                for (int kh = 0; kh < 3; kh++){
                    const u64 wl = wsp[S][o][i][kh*3+0];    // broadcast LDS.64
                    const u64 wc = wsp[S][o][i][kh*3+1];
                    const u64 wr = wsp[S][o][i][kh*3+2];
                    #pragma unroll
                    for (int r = 0; r < 4; r++){
                        A[o][r] = fma2(wl, Q0[r+kh], A[o][r]);
                        A[o][r] = fma2(wc, C [r+kh], A[o][r]);
                        A[o][r] = fma2(wr, Q1[r+kh], A[o][r]);
                    }
                }
            // residual for matching channel: src{c,c+1} at row y+r = C[r+1]
            #pragma unroll
            for (int r = 0; r < 4; r++) A[i][r] = add2(A[i][r], C[r+1]);
        }

        const int gxl = gx0 + c;
        #pragma unroll
        for (int o = 0; o < 3; o++)
            #pragma unroll
            for (int r = 0; r < 4; r++){
                const int Y = y + r;
                float lo, hi; unpack2(A[o][r], lo, hi);
                lo = lk(lo);
                hi = lk(hi);
                if (EDGE){
                    const int gy = gy0 + Y;
                    const bool iny = (unsigned)gy < (unsigned)HI;
                    if (!(iny && (unsigned)gxl     < (unsigned)WI)) lo = 0.f;
                    if (!(iny && (unsigned)(gxl+1) < (unsigned)WI)) hi = 0.f;
                }
                dst[o][Y][c]   = lo;
                dst[o][Y][c+1] = hi;
            }
    }
}

__device__ __forceinline__ float att_eval(const float* c, float h, float w, float xi)
{
    float Ah = fmaf(h, fmaf(c[0],h, fmaf(c[1],w, fmaf(c[2],xi,c[3]))),
               fmaf(w, fmaf(c[4],w, fmaf(c[5],xi,c[6])),
               fmaf(xi, fmaf(c[7],xi,c[8]), c[9])));
    float Bw = fmaf(w, fmaf(c[10],w, fmaf(c[11],xi,c[12])),
               fmaf(xi, fmaf(c[13],xi,c[14]), c[15]));
    float Cx = fmaf(xi, fmaf(c[16],xi,c[17]), c[18]);
    return fmaf(h, Ah, fmaf(w, Bw, fmaf(xi, Cx, c[19])));
}

template<bool EDGE>
__device__ __forceinline__ void run_stages(SMD& sm, int gy0, int gx0, int tid)
{
    stage<0,EDGE>(sm.a, sm.b, sm.wsp, sm.bsp, gy0, gx0, tid); __syncthreads();
    stage<1,EDGE>(sm.b, sm.a, sm.wsp, sm.bsp, gy0, gx0, tid); __syncthreads();
    stage<2,EDGE>(sm.a, sm.b, sm.wsp, sm.bsp, gy0, gx0, tid); __syncthreads();
    stage<3,EDGE>(sm.b, sm.a, sm.wsp, sm.bsp, gy0, gx0, tid); __syncthreads();
    stage<4,EDGE>(sm.a, sm.b, sm.wsp, sm.bsp, gy0, gx0, tid); __syncthreads();
}

__global__ __launch_bounds__(NT, 1)
void fused_kernel(const float* __restrict__ x,
                  const float* __restrict__ feature,
                  float* __restrict__ out)
{
    extern __shared__ char dsm_raw[];
    SMD& sm = *reinterpret_cast<SMD*>(dsm_raw);

    const int tile   = blockIdx.x;       // 0..255
    const int bidx   = blockIdx.y;       // 0..7
    const int tilesX = WI / TS;          // 16
    const int ty = tile / tilesX, tx = tile % tilesX;
    const int gy0 = ty*TS - HALO, gx0 = tx*TS - HALO;
    const int tid = threadIdx.x;
    const bool edge = (ty == 0) | (ty == tilesX-1) | (tx == 0) | (tx == tilesX-1);

    // feature -> splatted conv weights / biases + tail
    const float* fb = feature + bidx*492;
    for (int idx = tid; idx < 5*84; idx += NT){
        int s = idx / 84, j = idx % 84;
        float f = fb[s*84 + j];
        if (j < 81){
            int o = j / 27, i = (j % 27) / 9, t = j % 9;
            sm.wsp[s][o][i][t] = pack2(f, f);
        } else {
            sm.bsp[s][j-81] = pack2(f, f);
        }
    }
    for (int idx = tid; idx < 72; idx += NT) sm.ftail[idx] = fb[420 + idx];

    // input tile (zero-padded at image boundary) -> smem A rows 0..73
    const float* xb = x + (size_t)bidx*3*HW;
    for (int p = tid; p < 3*IT*IT; p += NT){
        int cch = p / (IT*IT);
        int r   = p % (IT*IT);
        int yy = r / IT, xx = r % IT;            // lanes -> xx: coalesced LDG
        int gy = gy0 + yy, gx = gx0 + xx;
        float v = 0.f;
        if (((unsigned)gy < (unsigned)HI) && ((unsigned)gx < (unsigned)WI))
            v = xb[(size_t)cch*HW + (size_t)gy*WI + gx];
        sm.a[cch][yy][xx] = v;
    }
    __syncthreads();

    if (edge) run_stages<true >(sm, gy0, gx0, tid);
    else      run_stages<false>(sm, gy0, gx0, tid);
    // result in sm.b, valid rows/cols [HALO, HALO+TS)

    float k1[9], b1[3];
    #pragma unroll
    for (int j = 0; j < 9; j++) k1[j] = sm.ftail[j];
    #pragma unroll
    for (int o = 0; o < 3; o++) b1[o] = sm.ftail[9 + o];
    float ca[20], cb[20], cc[20];
    #pragma unroll
    for (int j = 0; j < 20; j++){
        ca[j] = sm.ftail[12 + j];
        cb[j] = sm.ftail[32 + j];
        cc[j] = sm.ftail[52 + j];
    }

    const float invH = 1.0f / HI, invW = 1.0f / WI;
    for (int p = tid; p < TS*TS; p += NT){
        int y  = HALO + p / TS;
        int xq = HALO + p % TS;
        int gy = gy0 + y, gx = gx0 + xq;

        float v0 = sm.b[0][y][xq];
        float v1 = sm.b[1][y][xq];
        float v2 = sm.b[2][y][xq];

        float t0 = lk(v0 + k1[0]*v0 + k1[1]*v1 + k1[2]*v2 + b1[0]);
        float t1 = lk(v1 + k1[3]*v0 + k1[4]*v1 + k1[5]*v2 + b1[1]);
        float t2 = lk(v2 + k1[6]*v0 + k1[7]*v1 + k1[8]*v2 + b1[2]);

        size_t pix = (size_t)gy*WI + gx;
        float xf0 = xb[pix]        + t0;   // global residual (original x)
        float xf1 = xb[HW + pix]   + t1;
        float xf2 = xb[2*HW + pix] + t2;

        float h  = (float)gy * invH;
        float w_ = (float)gx * invW;

        size_t base = (size_t)bidx*3*HW + pix;
        out[base]        = fmaf(xf0, att_eval(ca, h, w_, xf0), xf0);
        out[base + HW]   = fmaf(xf1, att_eval(cb, h, w_, xf1), xf1);
        out[base + 2*HW] = fmaf(xf2, att_eval(cc, h, w_, xf2), xf2);
    }
}

__global__ void copy_thumb_kernel(const float4* __restrict__ src, float4* __restrict__ dst)
{
    int i = blockIdx.x * blockDim.x + threadIdx.x;
    if (i < NTHUMB/4) dst[i] = src[i];
}

extern "C" void kernel_launch(void* const* d_in, const int* in_sizes, int n_in,
                              void* d_out, int out_size)
{
    const float* x     = (const float*)d_in[0];
    const float* thumb = (const float*)d_in[1];
    const float* feat  = (const float*)d_in[2];
    float* out = (float*)d_out;

    // allow >48KB dynamic shared (idempotent; immediate host-side call, no graph node)
    cudaFuncSetAttribute(fused_kernel,
                         cudaFuncAttributeMaxDynamicSharedMemorySize,
                         (int)sizeof(SMD));

    // thumb copy FIRST so ncu's skip-5 sample lands on fused_kernel
    int nv4 = NTHUMB/4;
    copy_thumb_kernel<<<(nv4 + 255)/256, 256>>>((const float4*)thumb,
                                                (float4*)(out + NPIX));

    dim3 grid((HI/TS)*(WI/TS), 8);
    fused_kernel<<<grid, NT, sizeof(SMD)>>>(x, feat, out);
}

// round 15
// speedup vs baseline: 1.1255x; 1.0042x over previous
#include <cuda_runtime.h>

#define TS 64
#define HALO 5
#define IT 74                 // tile buffer 74x74
#define NT 768
#define HI 1024
#define WI 1024
#define HW (HI*WI)
#define NPIX (8*3*HW)         // 25165824
#define NTHUMB (8*3*256*256)  // 1572864

typedef unsigned long long u64;

__device__ __forceinline__ u64 pack2(float lo, float hi){
    u64 d;
    asm("mov.b64 %0, {%1, %2};" : "=l"(d)
        : "r"(__float_as_uint(lo)), "r"(__float_as_uint(hi)));
    return d;
}
__device__ __forceinline__ void unpack2(u64 v, float &lo, float &hi){
    unsigned a, b;
    asm("mov.b64 {%0, %1}, %2;" : "=r"(a), "=r"(b) : "l"(v));
    lo = __uint_as_float(a); hi = __uint_as_float(b);
}
// {hi(a), lo(b)}
__device__ __forceinline__ u64 pack_hl(u64 a, u64 b){
    unsigned a0,a1,b0,b1;
    asm("mov.b64 {%0,%1}, %2;" : "=r"(a0),"=r"(a1) : "l"(a));
    asm("mov.b64 {%0,%1}, %2;" : "=r"(b0),"=r"(b1) : "l"(b));
    u64 d; asm("mov.b64 %0, {%1,%2};" : "=l"(d) : "r"(a1),"r"(b0));
    return d;
}
__device__ __forceinline__ u64 fma2(u64 a, u64 b, u64 c){
    u64 d;
    asm("fma.rn.f32x2 %0, %1, %2, %3;" : "=l"(d) : "l"(a), "l"(b), "l"(c));
    return d;
}
__device__ __forceinline__ u64 add2(u64 a, u64 b){
    u64 d;
    asm("add.rn.f32x2 %0, %1, %2;" : "=l"(d) : "l"(a), "l"(b));
    return d;
}
__device__ __forceinline__ float lk(float v){ return fmaxf(v, 0.2f*v); } // exact leaky

struct SMD {
    u64   wsp[5][3][3][9];    // splatted conv3 weights {w,w} [S][o][i][kh*3+kw]
    u64   bsp[5][3];          // splatted biases
    float ftail[72];          // feat[420..491]
    float a[3][IT][IT];       // [ch][row][col] 65712 B
    float b[3][IT][IT];       //                65712 B
};                            // ~135.1 KB dynamic shared

// One residual 3x3 block: dst = leaky(src + conv3x3(src)), zero-masked to image.
// 2col x 4row micro-tile (8 px), col base odd: kw=-1 ({c-1,c}) / kw=+1
// ({c+1,c+2}) tap pairs are aligned LDS.64; center is one register merge;
// residual folded from center pairs. Shrinking regions: cols via QMIN=S>>1
// (36-2*QMIN pairs), rows [S+1 .. 72-S] in clamped 4-row groups. Junk/stale
// border cells advance inward >=1 px/stage; final valid region = [5,68]^2.
template<int S, bool EDGE>
__device__ __forceinline__ void stage(const float (&src)[3][IT][IT],
                                      float (&dst)[3][IT][IT],
                                      const u64 (&wsp)[5][3][3][9],
                                      const u64 (&bsp)[5][3],
                                      int gy0, int gx0, int tid)
{
    constexpr int QMIN = S >> 1;
    constexpr int NP   = 36 - 2*QMIN;        // col pairs: 36,36,34,34,32
    constexpr int NR   = 72 - 2*S;           // rows needed
    constexpr int RG   = (NR + 3) / 4;       // row groups: 18,18,17,17,16
    if (tid < NP*RG){
        const int c = 1 + 2*(QMIN + tid % NP);   // odd col base
        int y = (S + 1) + 4*(tid / NP);
        if (y > 69 - S) y = 69 - S;              // clamp: rows stay in [S+1,72-S]

        u64 A[3][4];
        #pragma unroll
        for (int o = 0; o < 3; o++){
            const u64 bb = bsp[S][o];
            #pragma unroll
            for (int r = 0; r < 4; r++) A[o][r] = bb;
        }

        #pragma unroll
        for (int i = 0; i < 3; i++){
            u64 Q0[6], Q1[6], C[6];              // rows y-1 .. y+4
            #pragma unroll
            for (int r = 0; r < 6; r++){
                Q0[r] = *(const u64*)&src[i][y-1+r][c-1];   // aligned {c-1,c}
                Q1[r] = *(const u64*)&src[i][y-1+r][c+1];   // aligned {c+1,c+2}
            }
            #pragma unroll
            for (int r = 0; r < 6; r++) C[r] = pack_hl(Q0[r], Q1[r]);  // {c,c+1}
            #pragma unroll
            for (int o = 0; o < 3; o++)
                #pragma unroll
                for (int kh = 0; kh < 3; kh++){
                    const u64 wl = wsp[S][o][i][kh*3+0];    // broadcast LDS.64
                    const u64 wc = wsp[S][o][i][kh*3+1];
                    const u64 wr = wsp[S][o][i][kh*3+2];
                    #pragma unroll
                    for (int r = 0; r < 4; r++){
                        A[o][r] = fma2(wl, Q0[r+kh], A[o][r]);
                        A[o][r] = fma2(wc, C [r+kh], A[o][r]);
                        A[o][r] = fma2(wr, Q1[r+kh], A[o][r]);
                    }
                }
            // residual for matching channel: src{c,c+1} at row y+r = C[r+1]
            #pragma unroll
            for (int r = 0; r < 4; r++) A[i][r] = add2(A[i][r], C[r+1]);
        }

        const int gxl = gx0 + c;
        #pragma unroll
        for (int o = 0; o < 3; o++)
            #pragma unroll
            for (int r = 0; r < 4; r++){
                const int Y = y + r;
                float lo, hi; unpack2(A[o][r], lo, hi);
                lo = lk(lo);
                hi = lk(hi);
                if (EDGE){
                    const int gy = gy0 + Y;
                    const bool iny = (unsigned)gy < (unsigned)HI;
                    if (!(iny && (unsigned)gxl     < (unsigned)WI)) lo = 0.f;
                    if (!(iny && (unsigned)(gxl+1) < (unsigned)WI)) hi = 0.f;
                }
                dst[o][Y][c]   = lo;
                dst[o][Y][c+1] = hi;
            }
    }
}

__device__ __forceinline__ float att_eval(const float* c, float h, float w, float xi)
{
    float Ah = fmaf(h, fmaf(c[0],h, fmaf(c[1],w, fmaf(c[2],xi,c[3]))),
               fmaf(w, fmaf(c[4],w, fmaf(c[5],xi,c[6])),
               fmaf(xi, fmaf(c[7],xi,c[8]), c[9])));
    float Bw = fmaf(w, fmaf(c[10],w, fmaf(c[11],xi,c[12])),
               fmaf(xi, fmaf(c[13],xi,c[14]), c[15]));
    float Cx = fmaf(xi, fmaf(c[16],xi,c[17]), c[18]);
    return fmaf(h, Ah, fmaf(w, Bw, fmaf(xi, Cx, c[19])));
}

template<bool EDGE>
__device__ __forceinline__ void run_stages(SMD& sm, int gy0, int gx0, int tid)
{
    stage<0,EDGE>(sm.a, sm.b, sm.wsp, sm.bsp, gy0, gx0, tid); __syncthreads();
    stage<1,EDGE>(sm.b, sm.a, sm.wsp, sm.bsp, gy0, gx0, tid); __syncthreads();
    stage<2,EDGE>(sm.a, sm.b, sm.wsp, sm.bsp, gy0, gx0, tid); __syncthreads();
    stage<3,EDGE>(sm.b, sm.a, sm.wsp, sm.bsp, gy0, gx0, tid); __syncthreads();
    stage<4,EDGE>(sm.a, sm.b, sm.wsp, sm.bsp, gy0, gx0, tid); __syncthreads();
}

__global__ __launch_bounds__(NT, 1)
void fused_kernel(const float* __restrict__ x,
                  const float* __restrict__ feature,
                  float* __restrict__ out)
{
    extern __shared__ char dsm_raw[];
    SMD& sm = *reinterpret_cast<SMD*>(dsm_raw);

    const int tile   = blockIdx.x;       // 0..255
    const int bidx   = blockIdx.y;       // 0..7
    const int tilesX = WI / TS;          // 16
    const int ty = tile / tilesX, tx = tile % tilesX;
    const int gy0 = ty*TS - HALO, gx0 = tx*TS - HALO;
    const int tid = threadIdx.x;
    const bool edge = (ty == 0) | (ty == tilesX-1) | (tx == 0) | (tx == tilesX-1);

    // feature -> splatted conv weights / biases + tail
    const float* fb = feature + bidx*492;
    for (int idx = tid; idx < 5*84; idx += NT){
        int s = idx / 84, j = idx % 84;
        float f = fb[s*84 + j];
        if (j < 81){
            int o = j / 27, i = (j % 27) / 9, t = j % 9;
            sm.wsp[s][o][i][t] = pack2(f, f);
        } else {
            sm.bsp[s][j-81] = pack2(f, f);
        }
    }
    for (int idx = tid; idx < 72; idx += NT) sm.ftail[idx] = fb[420 + idx];

    // input tile (zero-padded at image boundary) -> smem A rows 0..73
    const float* xb = x + (size_t)bidx*3*HW;
    for (int p = tid; p < 3*IT*IT; p += NT){
        int cch = p / (IT*IT);
        int r   = p % (IT*IT);
        int yy = r / IT, xx = r % IT;            // lanes -> xx: coalesced LDG
        int gy = gy0 + yy, gx = gx0 + xx;
        float v = 0.f;
        if (((unsigned)gy < (unsigned)HI) && ((unsigned)gx < (unsigned)WI))
            v = xb[(size_t)cch*HW + (size_t)gy*WI + gx];
        sm.a[cch][yy][xx] = v;
    }
    __syncthreads();

    if (edge) run_stages<true >(sm, gy0, gx0, tid);
    else      run_stages<false>(sm, gy0, gx0, tid);
    // result in sm.b, valid rows/cols [HALO, HALO+TS)

    float k1[9], b1[3];
    #pragma unroll
    for (int j = 0; j < 9; j++) k1[j] = sm.ftail[j];
    #pragma unroll
    for (int o = 0; o < 3; o++) b1[o] = sm.ftail[9 + o];
    float ca[20], cb[20], cc[20];
    #pragma unroll
    for (int j = 0; j < 20; j++){
        ca[j] = sm.ftail[12 + j];
        cb[j] = sm.ftail[32 + j];
        cc[j] = sm.ftail[52 + j];
    }

    const float invH = 1.0f / HI, invW = 1.0f / WI;
    for (int p = tid; p < TS*TS; p += NT){
        int y  = HALO + p / TS;
        int xq = HALO + p % TS;
        int gy = gy0 + y, gx = gx0 + xq;

        float v0 = sm.b[0][y][xq];
        float v1 = sm.b[1][y][xq];
        float v2 = sm.b[2][y][xq];

        float t0 = lk(v0 + k1[0]*v0 + k1[1]*v1 + k1[2]*v2 + b1[0]);
        float t1 = lk(v1 + k1[3]*v0 + k1[4]*v1 + k1[5]*v2 + b1[1]);
        float t2 = lk(v2 + k1[6]*v0 + k1[7]*v1 + k1[8]*v2 + b1[2]);

        size_t pix = (size_t)gy*WI + gx;
        float xf0 = xb[pix]        + t0;   // global residual (original x)
        float xf1 = xb[HW + pix]   + t1;
        float xf2 = xb[2*HW + pix] + t2;

        float h  = (float)gy * invH;
        float w_ = (float)gx * invW;

        size_t base = (size_t)bidx*3*HW + pix;
        out[base]        = fmaf(xf0, att_eval(ca, h, w_, xf0), xf0);
        out[base + HW]   = fmaf(xf1, att_eval(cb, h, w_, xf1), xf1);
        out[base + 2*HW] = fmaf(xf2, att_eval(cc, h, w_, xf2), xf2);
    }
}

__global__ void copy_thumb_kernel(const float4* __restrict__ src, float4* __restrict__ dst)
{
    int i = blockIdx.x * blockDim.x + threadIdx.x;
    if (i < NTHUMB/4) dst[i] = src[i];
}

extern "C" void kernel_launch(void* const* d_in, const int* in_sizes, int n_in,
                              void* d_out, int out_size)
{
    const float* x     = (const float*)d_in[0];
    const float* thumb = (const float*)d_in[1];
    const float* feat  = (const float*)d_in[2];
    float* out = (float*)d_out;

    // allow >48KB dynamic shared (idempotent; immediate host-side call, no graph node)
    cudaFuncSetAttribute(fused_kernel,
                         cudaFuncAttributeMaxDynamicSharedMemorySize,
                         (int)sizeof(SMD));

    // thumb copy FIRST so ncu's skip-5 sample lands on fused_kernel
    int nv4 = NTHUMB/4;
    copy_thumb_kernel<<<(nv4 + 255)/256, 256>>>((const float4*)thumb,
                                                (float4*)(out + NPIX));

    dim3 grid((HI/TS)*(WI/TS), 8);
    fused_kernel<<<grid, NT, sizeof(SMD)>>>(x, feat, out);
}